// round 12
// baseline (speedup 1.0000x reference)
#include <cuda_runtime.h>
#include <cuda_bf16.h>
#include <math.h>
#include <stdint.h>

#define BSZ 4096
#define NE  6
#define DF  1830
#define DPD 2086
#define DH  512

// Kpad: multiples of 64 (BK=64)
#define KP_I1 1088
#define KP_G1 1856
#define KP_E1 2112

#define RS        144     // smem row stride (128B data + 16B pad, conflict-free ldmatrix)
#define A_BYTES   18432   // 128 x 144
#define BLK_BYTES 36864   // B block: hi 128x144 | mid 128x144

// ---------------- scratch (device globals; no allocs allowed) ----------------
__device__ float g_h0 [BSZ*DPD];
__device__ float g_ih1[BSZ*256];
__device__ float g_ih2[BSZ*256];
__device__ float g_gh1[BSZ*512];
__device__ float g_gh2[BSZ*256];
__device__ float g_om [BSZ*NE];
__device__ float g_e1 [BSZ*DH];
__device__ float g_e2 [BSZ*DH];
__device__ float g_e3 [BSZ*DH];
__device__ float g_hd [BSZ*DF];
__device__ float g_hbias[DF];

// pre-packed weight blocks (chunk-exact smem images, bf16 hi|mid, 144B rows)
#define NB_I1 34      // 2 ct x 17 kc
#define NB_I2 8
#define NB_I3 8
#define NB_G1 116     // 4 x 29
#define NB_G2 16
#define NB_E1 792     // 4 x 33 x 6
#define NB_E2 192     // 4 x 8 x 6
#define NB_E3 192
#define NB_HD 120     // 15 x 8
__device__ __align__(128) unsigned char s_bi1[(size_t)NB_I1*BLK_BYTES];
__device__ __align__(128) unsigned char s_bi2[(size_t)NB_I2*BLK_BYTES];
__device__ __align__(128) unsigned char s_bi3[(size_t)NB_I3*BLK_BYTES];
__device__ __align__(128) unsigned char s_bg1[(size_t)NB_G1*BLK_BYTES];
__device__ __align__(128) unsigned char s_bg2[(size_t)NB_G2*BLK_BYTES];
__device__ __align__(128) unsigned char s_be1[(size_t)NB_E1*BLK_BYTES];
__device__ __align__(128) unsigned char s_be2[(size_t)NB_E2*BLK_BYTES];
__device__ __align__(128) unsigned char s_be3[(size_t)NB_E3*BLK_BYTES];
__device__ __align__(128) unsigned char s_bhd[(size_t)NB_HD*BLK_BYTES];

__device__ __forceinline__ float elu1(float x) { return x > 0.f ? x : expm1f(x); }

__device__ __forceinline__ uint32_t smem_u32(const void* p) {
    uint32_t a;
    asm("{ .reg .u64 t; cvta.to.shared.u64 t, %1; cvt.u32.u64 %0, t; }" : "=r"(a) : "l"(p));
    return a;
}
__device__ __forceinline__ uint32_t pack_split(float x0, float x1, uint32_t& mid) {
    __nv_bfloat16 h0 = __float2bfloat16(x0);
    __nv_bfloat16 h1 = __float2bfloat16(x1);
    float r0 = x0 - __bfloat162float(h0);
    float r1 = x1 - __bfloat162float(h1);
    __nv_bfloat16 m0 = __float2bfloat16(r0);
    __nv_bfloat16 m1 = __float2bfloat16(r1);
    mid = ((uint32_t)__bfloat16_as_ushort(m1) << 16) | __bfloat16_as_ushort(m0);
    return ((uint32_t)__bfloat16_as_ushort(h1) << 16) | __bfloat16_as_ushort(h0);
}
__device__ __forceinline__ void ldm4(uint32_t& r0, uint32_t& r1, uint32_t& r2, uint32_t& r3,
                                     uint32_t addr) {
    asm volatile("ldmatrix.sync.aligned.m8n8.x4.shared.b16 {%0,%1,%2,%3}, [%4];"
                 : "=r"(r0), "=r"(r1), "=r"(r2), "=r"(r3) : "r"(addr));
}
__device__ __forceinline__ void mma16816(float* d, const uint32_t* a, uint32_t b0, uint32_t b1) {
    asm volatile("mma.sync.aligned.m16n8k16.row.col.f32.bf16.bf16.f32 "
                 "{%0,%1,%2,%3}, {%4,%5,%6,%7}, {%8,%9}, {%0,%1,%2,%3};"
                 : "+f"(d[0]), "+f"(d[1]), "+f"(d[2]), "+f"(d[3])
                 : "r"(a[0]), "r"(a[1]), "r"(a[2]), "r"(a[3]), "r"(b0), "r"(b1));
}
__device__ __forceinline__ void mma16816_z(float* d, const uint32_t* a, uint32_t b0, uint32_t b1) {
    asm volatile("mma.sync.aligned.m16n8k16.row.col.f32.bf16.bf16.f32 "
                 "{%0,%1,%2,%3}, {%4,%5,%6,%7}, {%8,%9}, {%10,%11,%12,%13};"
                 : "=f"(d[0]), "=f"(d[1]), "=f"(d[2]), "=f"(d[3])
                 : "r"(a[0]), "r"(a[1]), "r"(a[2]), "r"(a[3]), "r"(b0), "r"(b1),
                   "f"(0.f), "f"(0.f), "f"(0.f), "f"(0.f));
}
__device__ __forceinline__ void mbar_init(uint32_t m, uint32_t cnt) {
    asm volatile("mbarrier.init.shared.b64 [%0], %1;" :: "r"(m), "r"(cnt) : "memory");
}
__device__ __forceinline__ void mbar_expect_tx(uint32_t m, uint32_t bytes) {
    asm volatile("mbarrier.arrive.expect_tx.shared.b64 _, [%0], %1;"
                 :: "r"(m), "r"(bytes) : "memory");
}
__device__ __forceinline__ void bulk_g2s(uint32_t dst, const void* src, uint32_t bytes, uint32_t m) {
    asm volatile("cp.async.bulk.shared::cluster.global.mbarrier::complete_tx::bytes "
                 "[%0], [%1], %2, [%3];"
                 :: "r"(dst), "l"(src), "r"(bytes), "r"(m) : "memory");
}
__device__ __forceinline__ void mbar_wait(uint32_t m, uint32_t ph) {
    asm volatile("{\n\t.reg .pred P;\n\tWL%=:\n\t"
        "mbarrier.try_wait.parity.acquire.cta.shared::cta.b64 P, [%0], %1, 0x989680;\n\t"
        "@P bra.uni WD%=;\n\tbra.uni WL%=;\n\tWD%=:\n\t}"
        :: "r"(m), "r"(ph) : "memory");
}

// ---------------- smem layout ----------------
constexpr int OFF_OM   = 0;          // 3072
constexpr int OFF_AH   = 3072;       // 18432
constexpr int OFF_AM   = 21504;      // 18432
constexpr int OFF_MBAR = 39936;      // 3 x 8B
constexpr int OFF_B    = 40064;      // 3 x 36864
constexpr int SMEM_BYTES = OFF_B + 3 * BLK_BYTES;   // 150656

// ---------------------------------------------------------------------------
// bf16x3 split GEMM, BK=64 chunks, cp.async.bulk B ring, term-major passes.
//   C[4096, Nw] = act( sum_e omega[:,e] * (A @ W_e) + bias )
// ---------------------------------------------------------------------------
__global__ void __launch_bounds__(256, 1) gemm_mma(
    const float* __restrict__ A, int lda,
    const float* __restrict__ A2, int K1,
    const unsigned char* __restrict__ Wblk,
    const float* __restrict__ omega,
    const float* __restrict__ bias,
    float* __restrict__ C, int ldc,
    int Nw, int K, int Kpad, int E, int blend, int doElu)
{
    extern __shared__ char smem[];
    const uint32_t sb = smem_u32(smem);
    float* omS = (float*)(smem + OFF_OM);

    const int tid  = threadIdx.x;
    const int lane = tid & 31, warp = tid >> 5;
    const int m_base = (warp & 3) * 32;
    const int n_base = (warp >> 2) * 64;
    const int rowBase = blockIdx.y * 128;
    const int colBase = blockIdx.x * 128;

    if (tid == 0) {
        mbar_init(sb + OFF_MBAR, 1);
        mbar_init(sb + OFF_MBAR + 8, 1);
        mbar_init(sb + OFF_MBAR + 16, 1);
        asm volatile("fence.proxy.async.shared::cta;" ::: "memory");
    }
    for (int i = tid; i < E * 128; i += 256) {
        int e = i >> 7, r = i & 127;
        omS[e * 128 + r] = omega ? omega[(size_t)(rowBase + r) * E + e] : 1.0f;
    }
    __syncthreads();

    float acc[2][8][4];
#pragma unroll
    for (int a = 0; a < 2; a++)
#pragma unroll
        for (int b = 0; b < 8; b++)
#pragma unroll
            for (int c = 0; c < 4; c++) acc[a][b][c] = 0.f;

    const int r  = tid >> 1, h = tid & 1;        // A staging: row, k-half(32)
    const int row = rowBase + r;
    const int lm = lane & 15, lc = lane >> 4;    // ldmatrix A mapping
    const int g  = lane >> 3;
    const int b_row  = ((g >> 1) << 3) + (lane & 7);
    const int b_koff = (g & 1) << 4;

    const int nKC = Kpad >> 6;
    const int NC = nKC * E;
    const unsigned char* Wct = Wblk + (size_t)blockIdx.x * NC * BLK_BYTES;

    auto issue = [&](int c) {
        uint32_t m = sb + OFF_MBAR + 8 * (c % 3);
        mbar_expect_tx(m, BLK_BYTES);
        bulk_g2s(sb + OFF_B + (c % 3) * BLK_BYTES, Wct + (size_t)c * BLK_BYTES, BLK_BYTES, m);
    };
    if (tid == 0) { issue(0); issue(1); }

    for (int c = 0; c < NC; c++) {
        const int e = c % E;
        mbar_wait(sb + OFF_MBAR + 8 * (c % 3), (c / 3) & 1);
        __syncthreads();

        if (e == 0) {
            // ---- A split for this 64-wide k-chunk ----
            const int k0 = (c / E) << 6;
            float v[32];
#pragma unroll
            for (int j = 0; j < 32; j++) {
                int k = k0 + h * 32 + j;
                float x = 0.f;
                if (k < K) x = (A2 && k >= K1) ? A2[row * 3 + (k - K1)]
                                               : A[(size_t)row * lda + k];
                v[j] = x;
            }
            uint32_t hi[16], mi[16];
#pragma unroll
            for (int u = 0; u < 16; u++) hi[u] = pack_split(v[2*u], v[2*u+1], mi[u]);
            char* dH = smem + OFF_AH + r * RS + h * 64;
            char* dM = smem + OFF_AM + r * RS + h * 64;
#pragma unroll
            for (int q = 0; q < 4; q++) {
                *(uint4*)(dH + q * 16) = make_uint4(hi[4*q], hi[4*q+1], hi[4*q+2], hi[4*q+3]);
                *(uint4*)(dM + q * 16) = make_uint4(mi[4*q], mi[4*q+1], mi[4*q+2], mi[4*q+3]);
            }
            __syncthreads();
        }

        // ---- MMA chunk into tmp (per-kh loads, term-major passes) ----
        float tmp[2][8][4];
        const uint32_t bhB = sb + OFF_B + (c % 3) * BLK_BYTES;
        const uint32_t bmB = bhB + A_BYTES;
#pragma unroll
        for (int kh = 0; kh < 4; kh++) {
            uint32_t ah[2][4], am[2][4];
#pragma unroll
            for (int m2 = 0; m2 < 2; m2++) {
                uint32_t ad = (m_base + m2 * 16 + lm) * RS + kh * 32 + lc * 16;
                ldm4(ah[m2][0], ah[m2][1], ah[m2][2], ah[m2][3], sb + OFF_AH + ad);
                ldm4(am[m2][0], am[m2][1], am[m2][2], am[m2][3], sb + OFF_AM + ad);
            }
            uint32_t bh[4][4], bm[4][4];
#pragma unroll
            for (int ni = 0; ni < 4; ni++) {
                uint32_t bd = (n_base + ni * 16 + b_row) * RS + kh * 32 + b_koff;
                ldm4(bh[ni][0], bh[ni][1], bh[ni][2], bh[ni][3], bhB + bd);
                ldm4(bm[ni][0], bm[ni][1], bm[ni][2], bm[ni][3], bmB + bd);
            }
            // pass 1: hi*hi
            if (kh == 0) {
#pragma unroll
                for (int ni = 0; ni < 4; ni++)
#pragma unroll
                    for (int m2 = 0; m2 < 2; m2++) {
                        mma16816_z(tmp[m2][2*ni],   ah[m2], bh[ni][0], bh[ni][1]);
                        mma16816_z(tmp[m2][2*ni+1], ah[m2], bh[ni][2], bh[ni][3]);
                    }
            } else {
#pragma unroll
                for (int ni = 0; ni < 4; ni++)
#pragma unroll
                    for (int m2 = 0; m2 < 2; m2++) {
                        mma16816(tmp[m2][2*ni],   ah[m2], bh[ni][0], bh[ni][1]);
                        mma16816(tmp[m2][2*ni+1], ah[m2], bh[ni][2], bh[ni][3]);
                    }
            }
            // pass 2: hi*mid
#pragma unroll
            for (int ni = 0; ni < 4; ni++)
#pragma unroll
                for (int m2 = 0; m2 < 2; m2++) {
                    mma16816(tmp[m2][2*ni],   ah[m2], bm[ni][0], bm[ni][1]);
                    mma16816(tmp[m2][2*ni+1], ah[m2], bm[ni][2], bm[ni][3]);
                }
            // pass 3: mid*hi
#pragma unroll
            for (int ni = 0; ni < 4; ni++)
#pragma unroll
                for (int m2 = 0; m2 < 2; m2++) {
                    mma16816(tmp[m2][2*ni],   am[m2], bh[ni][0], bh[ni][1]);
                    mma16816(tmp[m2][2*ni+1], am[m2], bh[ni][2], bh[ni][3]);
                }
        }
#pragma unroll
        for (int m2 = 0; m2 < 2; m2++) {
            float wA = omS[e * 128 + m_base + m2 * 16 + (lane >> 2)];
            float wB = omS[e * 128 + m_base + m2 * 16 + (lane >> 2) + 8];
#pragma unroll
            for (int nj = 0; nj < 8; nj++) {
                acc[m2][nj][0] += wA * tmp[m2][nj][0];
                acc[m2][nj][1] += wA * tmp[m2][nj][1];
                acc[m2][nj][2] += wB * tmp[m2][nj][2];
                acc[m2][nj][3] += wB * tmp[m2][nj][3];
            }
        }

        if (tid == 0 && c + 2 < NC) issue(c + 2);
    }

    // ---- epilogue ----
#pragma unroll
    for (int m2 = 0; m2 < 2; m2++) {
        int rlA = m_base + m2 * 16 + (lane >> 2);
        int rlB = rlA + 8;
#pragma unroll
        for (int nj = 0; nj < 8; nj++) {
            int n = colBase + n_base + nj * 8 + ((lane & 3) << 1);
            if (n >= Nw) continue;
            float bA0, bA1, bB0, bB1;
            if (blend) {
                bA0 = bA1 = bB0 = bB1 = 0.f;
                for (int e = 0; e < NE; e++) {
                    float be0 = bias[e * Nw + n], be1 = bias[e * Nw + n + 1];
                    bA0 += omS[e * 128 + rlA] * be0;  bA1 += omS[e * 128 + rlA] * be1;
                    bB0 += omS[e * 128 + rlB] * be0;  bB1 += omS[e * 128 + rlB] * be1;
                }
            } else {
                bA0 = bB0 = bias[n];
                bA1 = bB1 = bias[n + 1];
            }
            float v0 = acc[m2][nj][0] + bA0, v1 = acc[m2][nj][1] + bA1;
            float v2 = acc[m2][nj][2] + bB0, v3 = acc[m2][nj][3] + bB1;
            if (doElu) { v0 = elu1(v0); v1 = elu1(v1); v2 = elu1(v2); v3 = elu1(v3); }
            *(float2*)&C[(size_t)(rowBase + rlA) * ldc + n] = make_float2(v0, v1);
            *(float2*)&C[(size_t)(rowBase + rlB) * ldc + n] = make_float2(v2, v3);
        }
    }
}

// ---------------------------------------------------------------------------
// Weight prep: pack [E][K][Nw] fp32 -> 144B-row hi|mid block images (direct)
// ---------------------------------------------------------------------------
__global__ void prep_blocks(const float* __restrict__ W, unsigned char* __restrict__ dst,
                            int K, int Nw, int Kpad, int E) {
    const int nKC = Kpad >> 6;
    int blk = blockIdx.x;
    int e = blk % E;
    int kc = (blk / E) % nKC;
    int ct = blk / (E * nKC);
    unsigned char* d = dst + (size_t)blk * BLK_BYTES;
    for (int idx = threadIdx.x; idx < 128 * 18; idx += 256) {
        int n = idx / 18, q = idx % 18;        // q: 8B group within 144B row
        int gn = ct * 128 + n;
        uint32_t hw[2], mw[2];
#pragma unroll
        for (int u = 0; u < 2; u++) {
            uint32_t hx = 0, mx = 0;
#pragma unroll
            for (int s = 0; s < 2; s++) {
                int cc = q * 4 + u * 2 + s;
                float x = 0.f;
                if (cc < 64 && gn < Nw) {
                    int gk = kc * 64 + cc;
                    if (gk < K) x = W[((size_t)e * K + gk) * Nw + gn];
                }
                __nv_bfloat16 hh = __float2bfloat16(x);
                __nv_bfloat16 mm = __float2bfloat16(x - __bfloat162float(hh));
                hx |= (uint32_t)__bfloat16_as_ushort(hh) << (s * 16);
                mx |= (uint32_t)__bfloat16_as_ushort(mm) << (s * 16);
            }
            hw[u] = hx; mw[u] = mx;
        }
        *(uint2*)(d + n * RS + q * 8)           = make_uint2(hw[0], hw[1]);
        *(uint2*)(d + A_BYTES + n * RS + q * 8) = make_uint2(mw[0], mw[1]);
    }
}

__device__ __forceinline__ float head_w(const float* pw, const float* tw,
                                        const float* dw, const float* vw, int k, int n) {
    if (n < 330) return pw[k * 330 + n];
    if (n < 333) return tw[k * 3 + (n - 330)];
    if (n < 630) return dw[k * 297 + (n - 333)];
    return vw[(size_t)k * 1200 + (n - 630)];
}
__global__ void prep_blocks_hd(const float* __restrict__ pw, const float* __restrict__ tw,
                               const float* __restrict__ dw, const float* __restrict__ vw,
                               unsigned char* __restrict__ dst) {
    const int nKC = 8;
    int blk = blockIdx.x;
    int kc = blk % nKC;
    int ct = blk / nKC;
    unsigned char* d = dst + (size_t)blk * BLK_BYTES;
    for (int idx = threadIdx.x; idx < 128 * 18; idx += 256) {
        int n = idx / 18, q = idx % 18;
        int gn = ct * 128 + n;
        uint32_t hw[2], mw[2];
#pragma unroll
        for (int u = 0; u < 2; u++) {
            uint32_t hx = 0, mx = 0;
#pragma unroll
            for (int s = 0; s < 2; s++) {
                int cc = q * 4 + u * 2 + s;
                float x = 0.f;
                if (cc < 64 && gn < DF) x = head_w(pw, tw, dw, vw, kc * 64 + cc, gn);
                __nv_bfloat16 hh = __float2bfloat16(x);
                __nv_bfloat16 mm = __float2bfloat16(x - __bfloat162float(hh));
                hx |= (uint32_t)__bfloat16_as_ushort(hh) << (s * 16);
                mx |= (uint32_t)__bfloat16_as_ushort(mm) << (s * 16);
            }
            hw[u] = hx; mw[u] = mx;
        }
        *(uint2*)(d + n * RS + q * 8)           = make_uint2(hw[0], hw[1]);
        *(uint2*)(d + A_BYTES + n * RS + q * 8) = make_uint2(mw[0], mw[1]);
    }
}
__global__ void prep_hbias(const float* pb, const float* tb, const float* db, const float* vb,
                           float* out) {
    int n = blockIdx.x * 256 + threadIdx.x;
    if (n >= DF) return;
    float v;
    if (n < 330) v = pb[n];
    else if (n < 333) v = tb[n - 330];
    else if (n < 630) v = db[n - 333];
    else v = vb[n - 630];
    out[n] = v;
}

// ---------------------------------------------------------------------------
__global__ void assemble_frame(const float* __restrict__ rot, const float* __restrict__ tr,
                               const float* __restrict__ verts, const float* __restrict__ dists) {
    int idx = blockIdx.x * 256 + threadIdx.x;
    if (idx >= BSZ * DF) return;
    int b = idx / DF, c = idx % DF;
    float v;
    if (c < 330) {
        int j = c / 6, s = c % 6;
        v = rot[b * 495 + j * 9 + (s >> 1) * 3 + (s & 1)];
    } else if (c < 333) v = tr[b * 3 + (c - 330)];
    else if (c < 1533)  v = verts[b * 1200 + (c - 333)];
    else                v = dists[b * 297 + (c - 1533)];
    g_h0[(size_t)b * DPD + c] = v;
}

__global__ void gate3_softmax(const float* __restrict__ H, const float* __restrict__ W,
                              const float* __restrict__ b, float* __restrict__ om) {
    int warp = (blockIdx.x * blockDim.x + threadIdx.x) >> 5;
    int lane = threadIdx.x & 31;
    if (warp >= BSZ) return;
    float p[NE] = {};
    for (int k = lane; k < 256; k += 32) {
        float x = H[(size_t)warp * 256 + k];
#pragma unroll
        for (int e = 0; e < NE; e++) p[e] += x * W[k * NE + e];
    }
#pragma unroll
    for (int e = 0; e < NE; e++)
        for (int o = 16; o > 0; o >>= 1) p[e] += __shfl_down_sync(0xffffffffu, p[e], o);
    if (lane == 0) {
        float m = -1e30f;
#pragma unroll
        for (int e = 0; e < NE; e++) { p[e] += b[e]; m = fmaxf(m, p[e]); }
        float s = 0.f;
#pragma unroll
        for (int e = 0; e < NE; e++) { p[e] = expf(p[e] - m); s += p[e]; }
        float inv = 1.f / s;
#pragma unroll
        for (int e = 0; e < NE; e++) om[(size_t)warp * NE + e] = p[e] * inv;
    }
}

__global__ void post_pose(const float* __restrict__ hd, float* __restrict__ out) {
    int idx = blockIdx.x * 256 + threadIdx.x;
    if (idx >= BSZ * 55) return;
    int b = idx / 55, j = idx % 55;
    const float* p = hd + (size_t)b * DF + j * 6;
    float a1x = p[0], a2x = p[1], a1y = p[2], a2y = p[3], a1z = p[4], a2z = p[5];
    float inv = rsqrtf(a1x * a1x + a1y * a1y + a1z * a1z);
    float b1x = a1x * inv, b1y = a1y * inv, b1z = a1z * inv;
    float d = b1x * a2x + b1y * a2y + b1z * a2z;
    float cx = a2x - d * b1x, cy = a2y - d * b1y, cz = a2z - d * b1z;
    float inv2 = rsqrtf(cx * cx + cy * cy + cz * cz);
    float b2x = cx * inv2, b2y = cy * inv2, b2z = cz * inv2;
    float b3x = b1y * b2z - b1z * b2y;
    float b3y = b1z * b2x - b1x * b2z;
    float b3z = b1x * b2y - b1y * b2x;
    float* o = out + (size_t)b * 495 + j * 9;
    o[0] = b1x; o[1] = b2x; o[2] = b3x;
    o[3] = b1y; o[4] = b2y; o[5] = b3y;
    o[6] = b1z; o[7] = b2z; o[8] = b3z;
}

__global__ void post_copy(const float* __restrict__ hd, float* __restrict__ out) {
    const size_t base_t = (size_t)BSZ * 495;
    const size_t base_d = base_t + (size_t)BSZ * 3;
    const size_t base_v = base_d + (size_t)BSZ * 297;
    int idx = blockIdx.x * 256 + threadIdx.x;
    if (idx >= BSZ * 1500) return;
    int b = idx / 1500, c = idx % 1500;
    const float* row = hd + (size_t)b * DF;
    if (c < 3)        out[base_t + (size_t)b * 3 + c]            = row[330 + c];
    else if (c < 300) out[base_d + (size_t)b * 297 + (c - 3)]    = row[333 + (c - 3)];
    else              out[base_v + (size_t)b * 1200 + (c - 300)] = row[630 + (c - 300)];
}

// ---------------------------------------------------------------------------
extern "C" void kernel_launch(void* const* d_in, const int* in_sizes, int n_in,
                              void* d_out, int out_size) {
    const float* rot   = (const float*)d_in[0];
    const float* tr    = (const float*)d_in[1];
    const float* verts = (const float*)d_in[2];
    const float* dists = (const float*)d_in[3];
    const float* bps   = (const float*)d_in[4];
    const float* ogt   = (const float*)d_in[5];
    const float* iw1 = (const float*)d_in[6];  const float* ib1 = (const float*)d_in[7];
    const float* iw2 = (const float*)d_in[8];  const float* ib2 = (const float*)d_in[9];
    const float* iw3 = (const float*)d_in[10]; const float* ib3 = (const float*)d_in[11];
    const float* gw1 = (const float*)d_in[12]; const float* gb1 = (const float*)d_in[13];
    const float* gw2 = (const float*)d_in[14]; const float* gb2 = (const float*)d_in[15];
    const float* gw3 = (const float*)d_in[16]; const float* gb3 = (const float*)d_in[17];
    const float* ew1 = (const float*)d_in[18]; const float* eb1 = (const float*)d_in[19];
    const float* ew2 = (const float*)d_in[20]; const float* eb2 = (const float*)d_in[21];
    const float* ew3 = (const float*)d_in[22]; const float* eb3 = (const float*)d_in[23];
    const float* pw  = (const float*)d_in[24]; const float* pb  = (const float*)d_in[25];
    const float* tw  = (const float*)d_in[26]; const float* tb  = (const float*)d_in[27];
    const float* vw  = (const float*)d_in[28]; const float* vb  = (const float*)d_in[29];
    const float* dw  = (const float*)d_in[30]; const float* db  = (const float*)d_in[31];
    float* out = (float*)d_out;

    cudaFuncSetAttribute(gemm_mma, cudaFuncAttributeMaxDynamicSharedMemorySize, SMEM_BYTES);

    float *h0, *ih1, *ih2, *gh1, *gh2, *om, *e1, *e2, *e3, *hd, *hbias;
    cudaGetSymbolAddress((void**)&h0,  g_h0);
    cudaGetSymbolAddress((void**)&ih1, g_ih1);
    cudaGetSymbolAddress((void**)&ih2, g_ih2);
    cudaGetSymbolAddress((void**)&gh1, g_gh1);
    cudaGetSymbolAddress((void**)&gh2, g_gh2);
    cudaGetSymbolAddress((void**)&om,  g_om);
    cudaGetSymbolAddress((void**)&e1,  g_e1);
    cudaGetSymbolAddress((void**)&e2,  g_e2);
    cudaGetSymbolAddress((void**)&e3,  g_e3);
    cudaGetSymbolAddress((void**)&hd,  g_hd);
    cudaGetSymbolAddress((void**)&hbias, g_hbias);
    unsigned char *bi1,*bi2,*bi3,*bg1,*bg2,*be1,*be2,*be3,*bhd;
    cudaGetSymbolAddress((void**)&bi1, s_bi1);
    cudaGetSymbolAddress((void**)&bi2, s_bi2);
    cudaGetSymbolAddress((void**)&bi3, s_bi3);
    cudaGetSymbolAddress((void**)&bg1, s_bg1);
    cudaGetSymbolAddress((void**)&bg2, s_bg2);
    cudaGetSymbolAddress((void**)&be1, s_be1);
    cudaGetSymbolAddress((void**)&be2, s_be2);
    cudaGetSymbolAddress((void**)&be3, s_be3);
    cudaGetSymbolAddress((void**)&bhd, s_bhd);

    const int GY = BSZ / 128;  // 32

    // ---- ordered so the 6th launch (ncu -s 5 -c 1) is a mainloop GEMM ----
    prep_blocks<<<NB_G1, 256>>>(gw1, bg1, 1830, 512, KP_G1, 1);            // 1
    assemble_frame<<<(BSZ * DF + 255) / 256, 256>>>(rot, tr, verts, dists);// 2
    prep_blocks<<<NB_I1, 256>>>(iw1, bi1, 1027, 256, KP_I1, 1);            // 3
    prep_blocks<<<NB_I2, 256>>>(iw2, bi2, 256, 256, 256, 1);               // 4
    prep_blocks<<<NB_I3, 256>>>(iw3, bi3, 256, 256, 256, 1);               // 5
    gemm_mma<<<dim3(4, GY), 256, SMEM_BYTES>>>(h0, DPD, nullptr, 0, bg1, nullptr, gb1,
                                               gh1, 512, 512, 1830, KP_G1, 1, 0, 1);  // 6 (profiled)
    prep_blocks<<<NB_G2, 256>>>(gw2, bg2, 512, 256, 512, 1);
    prep_blocks<<<NB_E1, 256>>>(ew1, be1, 2086, 512, KP_E1, NE);
    prep_blocks<<<NB_E2, 256>>>(ew2, be2, 512, 512, 512, NE);
    prep_blocks<<<NB_E3, 256>>>(ew3, be3, 512, 512, 512, NE);
    prep_blocks_hd<<<NB_HD, 256>>>(pw, tw, dw, vw, bhd);
    prep_hbias<<<8, 256>>>(pb, tb, db, vb, hbias);

    gemm_mma<<<dim3(2, GY), 256, SMEM_BYTES>>>(bps, 1024, ogt, 1024, bi1, nullptr, ib1,
                                               ih1, 256, 256, 1027, KP_I1, 1, 0, 1);
    gemm_mma<<<dim3(2, GY), 256, SMEM_BYTES>>>(ih1, 256, nullptr, 0, bi2, nullptr, ib2,
                                               ih2, 256, 256, 256, 256, 1, 0, 1);
    gemm_mma<<<dim3(2, GY), 256, SMEM_BYTES>>>(ih2, 256, nullptr, 0, bi3, nullptr, ib3,
                                               h0 + 1830, DPD, 256, 256, 256, 1, 0, 1);
    gemm_mma<<<dim3(2, GY), 256, SMEM_BYTES>>>(gh1, 512, nullptr, 0, bg2, nullptr, gb2,
                                               gh2, 256, 256, 512, 512, 1, 0, 1);
    gate3_softmax<<<BSZ / 8, 256>>>(gh2, gw3, gb3, om);
    gemm_mma<<<dim3(4, GY), 256, SMEM_BYTES>>>(h0, DPD, nullptr, 0, be1, om, eb1,
                                               e1, DH, DH, DPD, KP_E1, NE, 1, 1);
    gemm_mma<<<dim3(4, GY), 256, SMEM_BYTES>>>(e1, DH, nullptr, 0, be2, om, eb2,
                                               e2, DH, DH, DH, DH, NE, 1, 1);
    gemm_mma<<<dim3(4, GY), 256, SMEM_BYTES>>>(e2, DH, nullptr, 0, be3, om, eb3,
                                               e3, DH, DH, DH, DH, NE, 1, 1);
    gemm_mma<<<dim3(15, GY), 256, SMEM_BYTES>>>(e3, DH, nullptr, 0, bhd, nullptr, hbias,
                                                hd, DF, DF, DH, DH, 1, 0, 0);
    post_pose<<<(BSZ * 55 + 255) / 256, 256>>>(hd, out);
    post_copy<<<(BSZ * 1500 + 255) / 256, 256>>>(hd, out);
}

// round 15
// speedup vs baseline: 1.0827x; 1.0827x over previous
#include <cuda_runtime.h>
#include <cuda_bf16.h>
#include <math.h>
#include <stdint.h>

#define BSZ 4096
#define NE  6
#define DF  1830
#define DPD 2086
#define DH  512

// Kpad: multiples of 64 (BK=64)
#define KP_I1 1088
#define KP_G1 1856
#define KP_E1 2112

#define RS        144     // smem row stride (128B data + 16B pad, conflict-free ldmatrix)
#define A_BYTES   18432   // 128 x 144
#define BLK_BYTES 36864   // B block: hi 128x144 | mid 128x144

// ---------------- scratch (device globals; no allocs allowed) ----------------
__device__ float g_h0 [BSZ*DPD];
__device__ float g_ih1[BSZ*256];
__device__ float g_ih2[BSZ*256];
__device__ float g_gh1[BSZ*512];
__device__ float g_gh2[BSZ*256];
__device__ float g_om [BSZ*NE];
__device__ float g_e1 [BSZ*DH];
__device__ float g_e2 [BSZ*DH];
__device__ float g_e3 [BSZ*DH];
__device__ float g_hd [BSZ*DF];
__device__ float g_hbias[DF];

// pre-packed weight blocks (chunk-exact smem images, bf16 hi|mid, 144B rows)
#define NB_I1 34      // 2 ct x 17 kc
#define NB_I2 8
#define NB_I3 8
#define NB_G1 116     // 4 x 29
#define NB_G2 16
#define NB_E1 792     // 4 x 33 x 6
#define NB_E2 192     // 4 x 8 x 6
#define NB_E3 192
#define NB_HD 120     // 15 x 8
__device__ __align__(128) unsigned char s_bi1[(size_t)NB_I1*BLK_BYTES];
__device__ __align__(128) unsigned char s_bi2[(size_t)NB_I2*BLK_BYTES];
__device__ __align__(128) unsigned char s_bi3[(size_t)NB_I3*BLK_BYTES];
__device__ __align__(128) unsigned char s_bg1[(size_t)NB_G1*BLK_BYTES];
__device__ __align__(128) unsigned char s_bg2[(size_t)NB_G2*BLK_BYTES];
__device__ __align__(128) unsigned char s_be1[(size_t)NB_E1*BLK_BYTES];
__device__ __align__(128) unsigned char s_be2[(size_t)NB_E2*BLK_BYTES];
__device__ __align__(128) unsigned char s_be3[(size_t)NB_E3*BLK_BYTES];
__device__ __align__(128) unsigned char s_bhd[(size_t)NB_HD*BLK_BYTES];

__device__ __forceinline__ float elu1(float x) { return x > 0.f ? x : expm1f(x); }

__device__ __forceinline__ uint32_t smem_u32(const void* p) {
    uint32_t a;
    asm("{ .reg .u64 t; cvta.to.shared.u64 t, %1; cvt.u32.u64 %0, t; }" : "=r"(a) : "l"(p));
    return a;
}
__device__ __forceinline__ uint32_t pack_split(float x0, float x1, uint32_t& mid) {
    __nv_bfloat16 h0 = __float2bfloat16(x0);
    __nv_bfloat16 h1 = __float2bfloat16(x1);
    float r0 = x0 - __bfloat162float(h0);
    float r1 = x1 - __bfloat162float(h1);
    __nv_bfloat16 m0 = __float2bfloat16(r0);
    __nv_bfloat16 m1 = __float2bfloat16(r1);
    mid = ((uint32_t)__bfloat16_as_ushort(m1) << 16) | __bfloat16_as_ushort(m0);
    return ((uint32_t)__bfloat16_as_ushort(h1) << 16) | __bfloat16_as_ushort(h0);
}
__device__ __forceinline__ void ldm4(uint32_t& r0, uint32_t& r1, uint32_t& r2, uint32_t& r3,
                                     uint32_t addr) {
    asm volatile("ldmatrix.sync.aligned.m8n8.x4.shared.b16 {%0,%1,%2,%3}, [%4];"
                 : "=r"(r0), "=r"(r1), "=r"(r2), "=r"(r3) : "r"(addr));
}
__device__ __forceinline__ void mma16816(float* d, const uint32_t* a, uint32_t b0, uint32_t b1) {
    asm volatile("mma.sync.aligned.m16n8k16.row.col.f32.bf16.bf16.f32 "
                 "{%0,%1,%2,%3}, {%4,%5,%6,%7}, {%8,%9}, {%0,%1,%2,%3};"
                 : "+f"(d[0]), "+f"(d[1]), "+f"(d[2]), "+f"(d[3])
                 : "r"(a[0]), "r"(a[1]), "r"(a[2]), "r"(a[3]), "r"(b0), "r"(b1));
}
__device__ __forceinline__ void mma16816_z(float* d, const uint32_t* a, uint32_t b0, uint32_t b1) {
    asm volatile("mma.sync.aligned.m16n8k16.row.col.f32.bf16.bf16.f32 "
                 "{%0,%1,%2,%3}, {%4,%5,%6,%7}, {%8,%9}, {%10,%11,%12,%13};"
                 : "=f"(d[0]), "=f"(d[1]), "=f"(d[2]), "=f"(d[3])
                 : "r"(a[0]), "r"(a[1]), "r"(a[2]), "r"(a[3]), "r"(b0), "r"(b1),
                   "f"(0.f), "f"(0.f), "f"(0.f), "f"(0.f));
}
__device__ __forceinline__ void mbar_init(uint32_t m, uint32_t cnt) {
    asm volatile("mbarrier.init.shared.b64 [%0], %1;" :: "r"(m), "r"(cnt) : "memory");
}
__device__ __forceinline__ void mbar_expect_tx(uint32_t m, uint32_t bytes) {
    asm volatile("mbarrier.arrive.expect_tx.shared.b64 _, [%0], %1;"
                 :: "r"(m), "r"(bytes) : "memory");
}
__device__ __forceinline__ void bulk_g2s(uint32_t dst, const void* src, uint32_t bytes, uint32_t m) {
    asm volatile("cp.async.bulk.shared::cluster.global.mbarrier::complete_tx::bytes "
                 "[%0], [%1], %2, [%3];"
                 :: "r"(dst), "l"(src), "r"(bytes), "r"(m) : "memory");
}
__device__ __forceinline__ void mbar_wait(uint32_t m, uint32_t ph) {
    asm volatile("{\n\t.reg .pred P;\n\tWL%=:\n\t"
        "mbarrier.try_wait.parity.acquire.cta.shared::cta.b64 P, [%0], %1, 0x989680;\n\t"
        "@P bra.uni WD%=;\n\tbra.uni WL%=;\n\tWD%=:\n\t}"
        :: "r"(m), "r"(ph) : "memory");
}

// ---------------- smem layout ----------------
constexpr int OFF_OM   = 0;          // 3072
constexpr int OFF_AH   = 3072;       // 18432
constexpr int OFF_AM   = 21504;      // 18432
constexpr int OFF_MBAR = 39936;      // 3 x 8B
constexpr int OFF_B    = 40064;      // 3 x 36864
constexpr int SMEM_BYTES = OFF_B + 3 * BLK_BYTES;   // 150656

// ---------------------------------------------------------------------------
// bf16x3 split GEMM, BK=64 chunks, cp.async.bulk B ring, term-major passes.
//   C[4096, Nw] = act( sum_e omega[:,e] * (A @ W_e) + bias )
// ---------------------------------------------------------------------------
__global__ void __launch_bounds__(256, 1) gemm_mma(
    const float* __restrict__ A, int lda,
    const float* __restrict__ A2, int K1,
    const unsigned char* __restrict__ Wblk,
    const float* __restrict__ omega,
    const float* __restrict__ bias,
    float* __restrict__ C, int ldc,
    int Nw, int K, int Kpad, int E, int blend, int doElu)
{
    extern __shared__ char smem[];
    const uint32_t sb = smem_u32(smem);
    float* omS = (float*)(smem + OFF_OM);

    const int tid  = threadIdx.x;
    const int lane = tid & 31, warp = tid >> 5;
    const int m_base = (warp & 3) * 32;
    const int n_base = (warp >> 2) * 64;
    const int rowBase = blockIdx.y * 128;
    const int colBase = blockIdx.x * 128;

    if (tid == 0) {
        mbar_init(sb + OFF_MBAR, 1);
        mbar_init(sb + OFF_MBAR + 8, 1);
        mbar_init(sb + OFF_MBAR + 16, 1);
        asm volatile("fence.proxy.async.shared::cta;" ::: "memory");
    }
    for (int i = tid; i < E * 128; i += 256) {
        int e = i >> 7, r = i & 127;
        omS[e * 128 + r] = omega ? omega[(size_t)(rowBase + r) * E + e] : 1.0f;
    }
    __syncthreads();

    float acc[2][8][4];
#pragma unroll
    for (int a = 0; a < 2; a++)
#pragma unroll
        for (int b = 0; b < 8; b++)
#pragma unroll
            for (int c = 0; c < 4; c++) acc[a][b][c] = 0.f;

    const int r  = tid >> 1, h = tid & 1;        // A staging: row, k-half(32)
    const int row = rowBase + r;
    const int lm = lane & 15, lc = lane >> 4;    // ldmatrix A mapping
    const int g  = lane >> 3;
    const int b_row  = ((g >> 1) << 3) + (lane & 7);
    const int b_koff = (g & 1) << 4;

    const int nKC = Kpad >> 6;
    const int NC = nKC * E;
    const unsigned char* Wct = Wblk + (size_t)blockIdx.x * NC * BLK_BYTES;

    auto issue = [&](int c) {
        uint32_t m = sb + OFF_MBAR + 8 * (c % 3);
        mbar_expect_tx(m, BLK_BYTES);
        bulk_g2s(sb + OFF_B + (c % 3) * BLK_BYTES, Wct + (size_t)c * BLK_BYTES, BLK_BYTES, m);
    };
    if (tid == 0) { issue(0); issue(1); }

    for (int c = 0; c < NC; c++) {
        const int e = c % E;
        mbar_wait(sb + OFF_MBAR + 8 * (c % 3), (c / 3) & 1);
        __syncthreads();

        if (e == 0) {
            // ---- A split for this 64-wide k-chunk ----
            const int k0 = (c / E) << 6;
            float v[32];
#pragma unroll
            for (int j = 0; j < 32; j++) {
                int k = k0 + h * 32 + j;
                float x = 0.f;
                if (k < K) x = (A2 && k >= K1) ? A2[row * 3 + (k - K1)]
                                               : A[(size_t)row * lda + k];
                v[j] = x;
            }
            uint32_t hi[16], mi[16];
#pragma unroll
            for (int u = 0; u < 16; u++) hi[u] = pack_split(v[2*u], v[2*u+1], mi[u]);
            char* dH = smem + OFF_AH + r * RS + h * 64;
            char* dM = smem + OFF_AM + r * RS + h * 64;
#pragma unroll
            for (int q = 0; q < 4; q++) {
                *(uint4*)(dH + q * 16) = make_uint4(hi[4*q], hi[4*q+1], hi[4*q+2], hi[4*q+3]);
                *(uint4*)(dM + q * 16) = make_uint4(mi[4*q], mi[4*q+1], mi[4*q+2], mi[4*q+3]);
            }
            __syncthreads();
        }

        // ---- MMA chunk into tmp (per-kh loads, term-major passes) ----
        float tmp[2][8][4];
        const uint32_t bhB = sb + OFF_B + (c % 3) * BLK_BYTES;
        const uint32_t bmB = bhB + A_BYTES;
#pragma unroll
        for (int kh = 0; kh < 4; kh++) {
            uint32_t ah[2][4], am[2][4];
#pragma unroll
            for (int m2 = 0; m2 < 2; m2++) {
                uint32_t ad = (m_base + m2 * 16 + lm) * RS + kh * 32 + lc * 16;
                ldm4(ah[m2][0], ah[m2][1], ah[m2][2], ah[m2][3], sb + OFF_AH + ad);
                ldm4(am[m2][0], am[m2][1], am[m2][2], am[m2][3], sb + OFF_AM + ad);
            }
            uint32_t bh[4][4], bm[4][4];
#pragma unroll
            for (int ni = 0; ni < 4; ni++) {
                uint32_t bd = (n_base + ni * 16 + b_row) * RS + kh * 32 + b_koff;
                ldm4(bh[ni][0], bh[ni][1], bh[ni][2], bh[ni][3], bhB + bd);
                ldm4(bm[ni][0], bm[ni][1], bm[ni][2], bm[ni][3], bmB + bd);
            }
            // pass 1: hi*hi
            if (kh == 0) {
#pragma unroll
                for (int ni = 0; ni < 4; ni++)
#pragma unroll
                    for (int m2 = 0; m2 < 2; m2++) {
                        mma16816_z(tmp[m2][2*ni],   ah[m2], bh[ni][0], bh[ni][1]);
                        mma16816_z(tmp[m2][2*ni+1], ah[m2], bh[ni][2], bh[ni][3]);
                    }
            } else {
#pragma unroll
                for (int ni = 0; ni < 4; ni++)
#pragma unroll
                    for (int m2 = 0; m2 < 2; m2++) {
                        mma16816(tmp[m2][2*ni],   ah[m2], bh[ni][0], bh[ni][1]);
                        mma16816(tmp[m2][2*ni+1], ah[m2], bh[ni][2], bh[ni][3]);
                    }
            }
            // pass 2: hi*mid
#pragma unroll
            for (int ni = 0; ni < 4; ni++)
#pragma unroll
                for (int m2 = 0; m2 < 2; m2++) {
                    mma16816(tmp[m2][2*ni],   ah[m2], bm[ni][0], bm[ni][1]);
                    mma16816(tmp[m2][2*ni+1], ah[m2], bm[ni][2], bm[ni][3]);
                }
            // pass 3: mid*hi
#pragma unroll
            for (int ni = 0; ni < 4; ni++)
#pragma unroll
                for (int m2 = 0; m2 < 2; m2++) {
                    mma16816(tmp[m2][2*ni],   am[m2], bh[ni][0], bh[ni][1]);
                    mma16816(tmp[m2][2*ni+1], am[m2], bh[ni][2], bh[ni][3]);
                }
        }
#pragma unroll
        for (int m2 = 0; m2 < 2; m2++) {
            float wA = omS[e * 128 + m_base + m2 * 16 + (lane >> 2)];
            float wB = omS[e * 128 + m_base + m2 * 16 + (lane >> 2) + 8];
#pragma unroll
            for (int nj = 0; nj < 8; nj++) {
                acc[m2][nj][0] += wA * tmp[m2][nj][0];
                acc[m2][nj][1] += wA * tmp[m2][nj][1];
                acc[m2][nj][2] += wB * tmp[m2][nj][2];
                acc[m2][nj][3] += wB * tmp[m2][nj][3];
            }
        }

        if (tid == 0 && c + 2 < NC) issue(c + 2);
    }

    // ---- epilogue ----
#pragma unroll
    for (int m2 = 0; m2 < 2; m2++) {
        int rlA = m_base + m2 * 16 + (lane >> 2);
        int rlB = rlA + 8;
#pragma unroll
        for (int nj = 0; nj < 8; nj++) {
            int n = colBase + n_base + nj * 8 + ((lane & 3) << 1);
            if (n >= Nw) continue;
            float bA0, bA1, bB0, bB1;
            if (blend) {
                bA0 = bA1 = bB0 = bB1 = 0.f;
                for (int e = 0; e < NE; e++) {
                    float be0 = bias[e * Nw + n], be1 = bias[e * Nw + n + 1];
                    bA0 += omS[e * 128 + rlA] * be0;  bA1 += omS[e * 128 + rlA] * be1;
                    bB0 += omS[e * 128 + rlB] * be0;  bB1 += omS[e * 128 + rlB] * be1;
                }
            } else {
                bA0 = bB0 = bias[n];
                bA1 = bB1 = bias[n + 1];
            }
            float v0 = acc[m2][nj][0] + bA0, v1 = acc[m2][nj][1] + bA1;
            float v2 = acc[m2][nj][2] + bB0, v3 = acc[m2][nj][3] + bB1;
            if (doElu) { v0 = elu1(v0); v1 = elu1(v1); v2 = elu1(v2); v3 = elu1(v3); }
            *(float2*)&C[(size_t)(rowBase + rlA) * ldc + n] = make_float2(v0, v1);
            *(float2*)&C[(size_t)(rowBase + rlB) * ldc + n] = make_float2(v2, v3);
        }
    }
}

// ---------------------------------------------------------------------------
// ONE fused prep kernel: all weight packs + head pack + hbias, block-dispatch.
// ---------------------------------------------------------------------------
__device__ __forceinline__ float head_w(const float* pw, const float* tw,
                                        const float* dw, const float* vw, int k, int n) {
    if (n < 330) return pw[k * 330 + n];
    if (n < 333) return tw[k * 3 + (n - 330)];
    if (n < 630) return dw[k * 297 + (n - 333)];
    return vw[(size_t)k * 1200 + (n - 630)];
}

__device__ void pack_one(const float* W, unsigned char* dst, int K, int Nw, int Kpad, int E,
                         int blk) {
    const int nKC = Kpad >> 6;
    int e = blk % E;
    int kc = (blk / E) % nKC;
    int ct = blk / (E * nKC);
    unsigned char* d = dst + (size_t)blk * BLK_BYTES;
    for (int idx = threadIdx.x; idx < 128 * 18; idx += 256) {
        int n = idx / 18, q = idx % 18;        // q: 8B group within 144B row
        int gn = ct * 128 + n;
        uint32_t hw[2], mw[2];
#pragma unroll
        for (int u = 0; u < 2; u++) {
            uint32_t hx = 0, mx = 0;
#pragma unroll
            for (int s = 0; s < 2; s++) {
                int cc = q * 4 + u * 2 + s;
                float x = 0.f;
                if (cc < 64 && gn < Nw) {
                    int gk = kc * 64 + cc;
                    if (gk < K) x = W[((size_t)e * K + gk) * Nw + gn];
                }
                __nv_bfloat16 hh = __float2bfloat16(x);
                __nv_bfloat16 mm = __float2bfloat16(x - __bfloat162float(hh));
                hx |= (uint32_t)__bfloat16_as_ushort(hh) << (s * 16);
                mx |= (uint32_t)__bfloat16_as_ushort(mm) << (s * 16);
            }
            hw[u] = hx; mw[u] = mx;
        }
        *(uint2*)(d + n * RS + q * 8)           = make_uint2(hw[0], hw[1]);
        *(uint2*)(d + A_BYTES + n * RS + q * 8) = make_uint2(mw[0], mw[1]);
    }
}

__device__ void pack_hd(const float* pw, const float* tw, const float* dw, const float* vw,
                        unsigned char* dst, int blk) {
    const int nKC = 8;
    int kc = blk % nKC;
    int ct = blk / nKC;
    unsigned char* d = dst + (size_t)blk * BLK_BYTES;
    for (int idx = threadIdx.x; idx < 128 * 18; idx += 256) {
        int n = idx / 18, q = idx % 18;
        int gn = ct * 128 + n;
        uint32_t hw[2], mw[2];
#pragma unroll
        for (int u = 0; u < 2; u++) {
            uint32_t hx = 0, mx = 0;
#pragma unroll
            for (int s = 0; s < 2; s++) {
                int cc = q * 4 + u * 2 + s;
                float x = 0.f;
                if (cc < 64 && gn < DF) x = head_w(pw, tw, dw, vw, kc * 64 + cc, gn);
                __nv_bfloat16 hh = __float2bfloat16(x);
                __nv_bfloat16 mm = __float2bfloat16(x - __bfloat162float(hh));
                hx |= (uint32_t)__bfloat16_as_ushort(hh) << (s * 16);
                mx |= (uint32_t)__bfloat16_as_ushort(mm) << (s * 16);
            }
            hw[u] = hx; mw[u] = mx;
        }
        *(uint2*)(d + n * RS + q * 8)           = make_uint2(hw[0], hw[1]);
        *(uint2*)(d + A_BYTES + n * RS + q * 8) = make_uint2(mw[0], mw[1]);
    }
}

// block ranges
#define RB_I1 0
#define RB_I2 (RB_I1 + NB_I1)       // 34
#define RB_I3 (RB_I2 + NB_I2)       // 42
#define RB_G1 (RB_I3 + NB_I3)       // 50
#define RB_G2 (RB_G1 + NB_G1)       // 166
#define RB_E1 (RB_G2 + NB_G2)       // 182
#define RB_E2 (RB_E1 + NB_E1)       // 974
#define RB_E3 (RB_E2 + NB_E2)       // 1166
#define RB_HD (RB_E3 + NB_E3)       // 1358
#define RB_HB (RB_HD + NB_HD)       // 1478
#define NB_ALL (RB_HB + 8)          // 1486

__global__ void __launch_bounds__(256) prep_all(
    const float* iw1, const float* iw2, const float* iw3,
    const float* gw1, const float* gw2,
    const float* ew1, const float* ew2, const float* ew3,
    const float* pw, const float* tw, const float* dw, const float* vw,
    const float* pb, const float* tb, const float* db, const float* vb,
    unsigned char* bi1, unsigned char* bi2, unsigned char* bi3,
    unsigned char* bg1, unsigned char* bg2,
    unsigned char* be1, unsigned char* be2, unsigned char* be3,
    unsigned char* bhd, float* hbias)
{
    int b = blockIdx.x;
    if      (b < RB_I2) pack_one(iw1, bi1, 1027, 256, KP_I1, 1, b - RB_I1);
    else if (b < RB_I3) pack_one(iw2, bi2, 256, 256, 256, 1, b - RB_I2);
    else if (b < RB_G1) pack_one(iw3, bi3, 256, 256, 256, 1, b - RB_I3);
    else if (b < RB_G2) pack_one(gw1, bg1, 1830, 512, KP_G1, 1, b - RB_G1);
    else if (b < RB_E1) pack_one(gw2, bg2, 512, 256, 512, 1, b - RB_G2);
    else if (b < RB_E2) pack_one(ew1, be1, 2086, 512, KP_E1, NE, b - RB_E1);
    else if (b < RB_E3) pack_one(ew2, be2, 512, 512, 512, NE, b - RB_E2);
    else if (b < RB_HD) pack_one(ew3, be3, 512, 512, 512, NE, b - RB_E3);
    else if (b < RB_HB) pack_hd(pw, tw, dw, vw, bhd, b - RB_HD);
    else {
        int n = (b - RB_HB) * 256 + threadIdx.x;
        if (n < DF) {
            float v;
            if (n < 330) v = pb[n];
            else if (n < 333) v = tb[n - 330];
            else if (n < 630) v = db[n - 333];
            else v = vb[n - 630];
            hbias[n] = v;
        }
    }
}

// ---------------------------------------------------------------------------
__global__ void assemble_frame(const float* __restrict__ rot, const float* __restrict__ tr,
                               const float* __restrict__ verts, const float* __restrict__ dists) {
    int idx = blockIdx.x * 256 + threadIdx.x;
    if (idx >= BSZ * DF) return;
    int b = idx / DF, c = idx % DF;
    float v;
    if (c < 330) {
        int j = c / 6, s = c % 6;
        v = rot[b * 495 + j * 9 + (s >> 1) * 3 + (s & 1)];
    } else if (c < 333) v = tr[b * 3 + (c - 330)];
    else if (c < 1533)  v = verts[b * 1200 + (c - 333)];
    else                v = dists[b * 297 + (c - 1533)];
    g_h0[(size_t)b * DPD + c] = v;
}

__global__ void gate3_softmax(const float* __restrict__ H, const float* __restrict__ W,
                              const float* __restrict__ b, float* __restrict__ om) {
    int warp = (blockIdx.x * blockDim.x + threadIdx.x) >> 5;
    int lane = threadIdx.x & 31;
    if (warp >= BSZ) return;
    float p[NE] = {};
    for (int k = lane; k < 256; k += 32) {
        float x = H[(size_t)warp * 256 + k];
#pragma unroll
        for (int e = 0; e < NE; e++) p[e] += x * W[k * NE + e];
    }
#pragma unroll
    for (int e = 0; e < NE; e++)
        for (int o = 16; o > 0; o >>= 1) p[e] += __shfl_down_sync(0xffffffffu, p[e], o);
    if (lane == 0) {
        float m = -1e30f;
#pragma unroll
        for (int e = 0; e < NE; e++) { p[e] += b[e]; m = fmaxf(m, p[e]); }
        float s = 0.f;
#pragma unroll
        for (int e = 0; e < NE; e++) { p[e] = expf(p[e] - m); s += p[e]; }
        float inv = 1.f / s;
#pragma unroll
        for (int e = 0; e < NE; e++) om[(size_t)warp * NE + e] = p[e] * inv;
    }
}

__global__ void post_pose(const float* __restrict__ hd, float* __restrict__ out) {
    int idx = blockIdx.x * 256 + threadIdx.x;
    if (idx >= BSZ * 55) return;
    int b = idx / 55, j = idx % 55;
    const float* p = hd + (size_t)b * DF + j * 6;
    float a1x = p[0], a2x = p[1], a1y = p[2], a2y = p[3], a1z = p[4], a2z = p[5];
    float inv = rsqrtf(a1x * a1x + a1y * a1y + a1z * a1z);
    float b1x = a1x * inv, b1y = a1y * inv, b1z = a1z * inv;
    float d = b1x * a2x + b1y * a2y + b1z * a2z;
    float cx = a2x - d * b1x, cy = a2y - d * b1y, cz = a2z - d * b1z;
    float inv2 = rsqrtf(cx * cx + cy * cy + cz * cz);
    float b2x = cx * inv2, b2y = cy * inv2, b2z = cz * inv2;
    float b3x = b1y * b2z - b1z * b2y;
    float b3y = b1z * b2x - b1x * b2z;
    float b3z = b1x * b2y - b1y * b2x;
    float* o = out + (size_t)b * 495 + j * 9;
    o[0] = b1x; o[1] = b2x; o[2] = b3x;
    o[3] = b1y; o[4] = b2y; o[5] = b3y;
    o[6] = b1z; o[7] = b2z; o[8] = b3z;
}

__global__ void post_copy(const float* __restrict__ hd, float* __restrict__ out) {
    const size_t base_t = (size_t)BSZ * 495;
    const size_t base_d = base_t + (size_t)BSZ * 3;
    const size_t base_v = base_d + (size_t)BSZ * 297;
    int idx = blockIdx.x * 256 + threadIdx.x;
    if (idx >= BSZ * 1500) return;
    int b = idx / 1500, c = idx % 1500;
    const float* row = hd + (size_t)b * DF;
    if (c < 3)        out[base_t + (size_t)b * 3 + c]            = row[330 + c];
    else if (c < 300) out[base_d + (size_t)b * 297 + (c - 3)]    = row[333 + (c - 3)];
    else              out[base_v + (size_t)b * 1200 + (c - 300)] = row[630 + (c - 300)];
}

// ---------------------------------------------------------------------------
extern "C" void kernel_launch(void* const* d_in, const int* in_sizes, int n_in,
                              void* d_out, int out_size) {
    const float* rot   = (const float*)d_in[0];
    const float* tr    = (const float*)d_in[1];
    const float* verts = (const float*)d_in[2];
    const float* dists = (const float*)d_in[3];
    const float* bps   = (const float*)d_in[4];
    const float* ogt   = (const float*)d_in[5];
    const float* iw1 = (const float*)d_in[6];  const float* ib1 = (const float*)d_in[7];
    const float* iw2 = (const float*)d_in[8];  const float* ib2 = (const float*)d_in[9];
    const float* iw3 = (const float*)d_in[10]; const float* ib3 = (const float*)d_in[11];
    const float* gw1 = (const float*)d_in[12]; const float* gb1 = (const float*)d_in[13];
    const float* gw2 = (const float*)d_in[14]; const float* gb2 = (const float*)d_in[15];
    const float* gw3 = (const float*)d_in[16]; const float* gb3 = (const float*)d_in[17];
    const float* ew1 = (const float*)d_in[18]; const float* eb1 = (const float*)d_in[19];
    const float* ew2 = (const float*)d_in[20]; const float* eb2 = (const float*)d_in[21];
    const float* ew3 = (const float*)d_in[22]; const float* eb3 = (const float*)d_in[23];
    const float* pw  = (const float*)d_in[24]; const float* pb  = (const float*)d_in[25];
    const float* tw  = (const float*)d_in[26]; const float* tb  = (const float*)d_in[27];
    const float* vw  = (const float*)d_in[28]; const float* vb  = (const float*)d_in[29];
    const float* dw  = (const float*)d_in[30]; const float* db  = (const float*)d_in[31];
    float* out = (float*)d_out;

    cudaFuncSetAttribute(gemm_mma, cudaFuncAttributeMaxDynamicSharedMemorySize, SMEM_BYTES);

    float *h0, *ih1, *ih2, *gh1, *gh2, *om, *e1, *e2, *e3, *hd, *hbias;
    cudaGetSymbolAddress((void**)&h0,  g_h0);
    cudaGetSymbolAddress((void**)&ih1, g_ih1);
    cudaGetSymbolAddress((void**)&ih2, g_ih2);
    cudaGetSymbolAddress((void**)&gh1, g_gh1);
    cudaGetSymbolAddress((void**)&gh2, g_gh2);
    cudaGetSymbolAddress((void**)&om,  g_om);
    cudaGetSymbolAddress((void**)&e1,  g_e1);
    cudaGetSymbolAddress((void**)&e2,  g_e2);
    cudaGetSymbolAddress((void**)&e3,  g_e3);
    cudaGetSymbolAddress((void**)&hd,  g_hd);
    cudaGetSymbolAddress((void**)&hbias, g_hbias);
    unsigned char *bi1,*bi2,*bi3,*bg1,*bg2,*be1,*be2,*be3,*bhd;
    cudaGetSymbolAddress((void**)&bi1, s_bi1);
    cudaGetSymbolAddress((void**)&bi2, s_bi2);
    cudaGetSymbolAddress((void**)&bi3, s_bi3);
    cudaGetSymbolAddress((void**)&bg1, s_bg1);
    cudaGetSymbolAddress((void**)&bg2, s_bg2);
    cudaGetSymbolAddress((void**)&be1, s_be1);
    cudaGetSymbolAddress((void**)&be2, s_be2);
    cudaGetSymbolAddress((void**)&be3, s_be3);
    cudaGetSymbolAddress((void**)&bhd, s_bhd);

    const int GY = BSZ / 128;  // 32

    // ONE fused prep launch + frame assembly
    prep_all<<<NB_ALL, 256>>>(iw1, iw2, iw3, gw1, gw2, ew1, ew2, ew3,
                              pw, tw, dw, vw, pb, tb, db, vb,
                              bi1, bi2, bi3, bg1, bg2, be1, be2, be3, bhd, hbias);
    assemble_frame<<<(BSZ * DF + 255) / 256, 256>>>(rot, tr, verts, dists);

    gemm_mma<<<dim3(2, GY), 256, SMEM_BYTES>>>(bps, 1024, ogt, 1024, bi1, nullptr, ib1,
                                               ih1, 256, 256, 1027, KP_I1, 1, 0, 1);
    gemm_mma<<<dim3(2, GY), 256, SMEM_BYTES>>>(ih1, 256, nullptr, 0, bi2, nullptr, ib2,
                                               ih2, 256, 256, 256, 256, 1, 0, 1);
    gemm_mma<<<dim3(2, GY), 256, SMEM_BYTES>>>(ih2, 256, nullptr, 0, bi3, nullptr, ib3,
                                               h0 + 1830, DPD, 256, 256, 256, 1, 0, 1);
    gemm_mma<<<dim3(4, GY), 256, SMEM_BYTES>>>(h0, DPD, nullptr, 0, bg1, nullptr, gb1,
                                               gh1, 512, 512, 1830, KP_G1, 1, 0, 1);
    gemm_mma<<<dim3(2, GY), 256, SMEM_BYTES>>>(gh1, 512, nullptr, 0, bg2, nullptr, gb2,
                                               gh2, 256, 256, 512, 512, 1, 0, 1);
    gate3_softmax<<<BSZ / 8, 256>>>(gh2, gw3, gb3, om);
    gemm_mma<<<dim3(4, GY), 256, SMEM_BYTES>>>(h0, DPD, nullptr, 0, be1, om, eb1,
                                               e1, DH, DH, DPD, KP_E1, NE, 1, 1);
    gemm_mma<<<dim3(4, GY), 256, SMEM_BYTES>>>(e1, DH, nullptr, 0, be2, om, eb2,
                                               e2, DH, DH, DH, DH, NE, 1, 1);
    gemm_mma<<<dim3(4, GY), 256, SMEM_BYTES>>>(e2, DH, nullptr, 0, be3, om, eb3,
                                               e3, DH, DH, DH, DH, NE, 1, 1);
    gemm_mma<<<dim3(15, GY), 256, SMEM_BYTES>>>(e3, DH, nullptr, 0, bhd, nullptr, hbias,
                                                hd, DF, DF, DH, DH, 1, 0, 0);
    post_pose<<<(BSZ * 55 + 255) / 256, 256>>>(hd, out);
    post_copy<<<(BSZ * 1500 + 255) / 256, 256>>>(hd, out);
}